// round 4
// baseline (speedup 1.0000x reference)
#include <cuda_runtime.h>

// ---------------------------------------------------------------------------
// EResidualBlockBucket: x -> grouped3x3+ReLU -> per-pixel bucket-indexed
// dynamic 3x3 conv (+per-pixel bias) -> ReLU -> 1x1 conv -> +x -> ReLU
//
// Strategy: bucket-major processing. One CTA per bucket type builds its pixel
// list in smem, stages patches (pixel-major h layout -> coalesced float4
// gather) and weights (aligned smem -> LDS.128 uniform) and does the 577-deep
// dot products with fp32 FMA. emb (32MB) is read exactly once per launch.
// ---------------------------------------------------------------------------

#define HPW 66                 // padded image width/height
#define HPSZ (64 * HPW * HPW)  // h_pad elements: [y][x][ic], ic fastest

__device__ __align__(16) float g_hpad[HPSZ];     // padded h, pixel-major
__device__ __align__(16) float g_dyn[64 * 4096]; // dynamic conv out [oc][pix]

// ---------------- K0: zero padded h buffer ---------------------------------
__global__ void k_zero(void) {
    int i = blockIdx.x * blockDim.x + threadIdx.x;
    if (i < HPSZ) g_hpad[i] = 0.0f;
}

// ---------------- K1: grouped 3x3 conv + bias + ReLU -> g_hpad -------------
// grid: 64 blocks = 4 groups x 16 tiles (16x16 px). 256 threads.
__global__ void __launch_bounds__(256) k_gconv(const float* __restrict__ x,
                                               const float* __restrict__ w1,
                                               const float* __restrict__ b1) {
    __shared__ float xs[16][18][18];   // input tile + halo, one group (16 ic)
    __shared__ float ws[16][144];      // weights for 16 oc of this group
    __shared__ float bs[16];

    int bx = blockIdx.x;
    int g = bx >> 4;                   // group 0..3
    int tile = bx & 15;
    int y0 = (tile >> 2) * 16, x0 = (tile & 3) * 16;
    int tid = threadIdx.x;

    for (int i = tid; i < 16 * 18 * 18; i += 256) {
        int ic = i / 324;
        int rem = i - ic * 324;
        int r = rem / 18, c = rem - r * 18;
        int yy = y0 - 1 + r, xx = x0 - 1 + c;
        float v = 0.f;
        if (yy >= 0 && yy < 64 && xx >= 0 && xx < 64)
            v = x[(g * 16 + ic) * 4096 + yy * 64 + xx];
        xs[ic][r][c] = v;
    }
    for (int i = tid; i < 16 * 144; i += 256) {
        int oc = i / 144;
        ws[oc][i - oc * 144] = w1[(g * 16 + oc) * 144 + (i - oc * 144)];
    }
    if (tid < 16) bs[tid] = b1[g * 16 + tid];
    __syncthreads();

    int r = tid >> 4, c = tid & 15;
    float acc[16];
#pragma unroll
    for (int j = 0; j < 16; ++j) acc[j] = bs[j];

    for (int ic = 0; ic < 16; ++ic) {
        float p[9];
#pragma unroll
        for (int dy = 0; dy < 3; ++dy)
#pragma unroll
            for (int dx = 0; dx < 3; ++dx)
                p[dy * 3 + dx] = xs[ic][r + dy][c + dx];
#pragma unroll
        for (int j = 0; j < 16; ++j) {
#pragma unroll
            for (int k = 0; k < 9; ++k)
                acc[j] = fmaf(ws[j][ic * 9 + k], p[k], acc[j]);
        }
    }
    // write pixel-major padded layout: h_pad[((y+1)*66 + (x+1))*64 + oc]
    float* dst = g_hpad + (((y0 + r + 1) * HPW) + (x0 + c + 1)) * 64 + g * 16;
#pragma unroll
    for (int j = 0; j < 16; ++j) dst[j] = fmaxf(acc[j], 0.f);
}

// ---------------- K2: bucket-grouped dynamic conv --------------------------
// grid: 216 blocks (one per type), 256 threads (8 warps, each warp -> 8 ocs,
// lanes -> pixels of this type, processed in chunks of 32).
__global__ void __launch_bounds__(256) k_dyn(const int* __restrict__ buckets,
                                             const float* __restrict__ emb) {
    // Shared arrays used with float4 (LDS.128/STS.128) MUST be 16B aligned;
    // plain __shared__ float[] is only 4B aligned -> misaligned-address trap.
    __shared__ __align__(16) float ws[64 * 72];  // weights: [oc][c_local]
    __shared__ __align__(16) float ps[72 * 33];  // patches: [c_local][pixel]
    __shared__ unsigned short plist[4096];
    __shared__ int s_count;

    int t = blockIdx.x;
    int tid = threadIdx.x;
    if (tid == 0) s_count = 0;
    __syncthreads();
    for (int i = tid; i < 4096; i += 256) {
        if (buckets[i] == t) {
            int p = atomicAdd(&s_count, 1);
            plist[p] = (unsigned short)i;
        }
    }
    __syncthreads();
    int n = s_count;
    if (n == 0) return;

    int lane = tid & 31;
    int oc_base = (tid >> 5) * 8;
    const float* W = emb + (size_t)t * 36928;

    for (int chunk = 0; chunk < n; chunk += 32) {
        int pi = chunk + lane;
        int mypix = plist[pi < n ? pi : n - 1];

        float acc[8];
#pragma unroll
        for (int j = 0; j < 8; ++j)
            acc[j] = __ldg(W + (oc_base + j) * 577 + 576);  // per-pixel bias

        for (int icc8 = 0; icc8 < 8; ++icc8) {
            int icc = icc8 * 8;  // ic chunk [icc, icc+8)

            // ---- stage patches: 32 px x 9 positions x 8 ic = 576 float4s
            for (int t2 = tid; t2 < 576; t2 += 256) {
                int q = t2 & 1;
                int r = t2 >> 1;          // 0..287
                int slot = r / 9;
                int pos = r - slot * 9;   // dy*3+dx
                int pj = chunk + slot;
                int pix = plist[pj < n ? pj : n - 1];
                int y = pix >> 6, xx = pix & 63;
                int dy = pos / 3, dx = pos - dy * 3;
                const float4 v = *(const float4*)(g_hpad +
                    (((y + dy) * HPW) + (xx + dx)) * 64 + icc + q * 4);
                int base_ic = q * 4;
                ps[((base_ic + 0) * 9 + pos) * 33 + slot] = v.x;
                ps[((base_ic + 1) * 9 + pos) * 33 + slot] = v.y;
                ps[((base_ic + 2) * 9 + pos) * 33 + slot] = v.z;
                ps[((base_ic + 3) * 9 + pos) * 33 + slot] = v.w;
            }
            // ---- stage weights: 64 oc x 72 c
            {
                const float* Wc = W + icc * 9;
                for (int i2 = tid; i2 < 4608; i2 += 256) {
                    int oc = i2 / 72;
                    int cl = i2 - oc * 72;
                    ws[i2] = __ldg(Wc + oc * 577 + cl);
                }
            }
            __syncthreads();

            // ---- compute: 72 c x 8 oc per warp, weights via LDS.128
            const float* psl = ps + lane;
#pragma unroll 3
            for (int c4 = 0; c4 < 72; c4 += 4) {
                float pv0 = psl[(c4 + 0) * 33];
                float pv1 = psl[(c4 + 1) * 33];
                float pv2 = psl[(c4 + 2) * 33];
                float pv3 = psl[(c4 + 3) * 33];
#pragma unroll
                for (int j = 0; j < 8; ++j) {
                    float4 w = *(const float4*)&ws[(oc_base + j) * 72 + c4];
                    acc[j] = fmaf(w.x, pv0, acc[j]);
                    acc[j] = fmaf(w.y, pv1, acc[j]);
                    acc[j] = fmaf(w.z, pv2, acc[j]);
                    acc[j] = fmaf(w.w, pv3, acc[j]);
                }
            }
            __syncthreads();
        }

        if (pi < n) {
#pragma unroll
            for (int j = 0; j < 8; ++j)
                g_dyn[(oc_base + j) * 4096 + mypix] = acc[j];
        }
    }
}

// ---------------- K3: ReLU -> 1x1 conv + b2 -> +x -> ReLU ------------------
// grid: 64 blocks x 256 threads. block = 64 pixels; thread = (pixel, 16 ocs).
__global__ void __launch_bounds__(256) k_epi(const float* __restrict__ x,
                                             const float* __restrict__ w2,
                                             const float* __restrict__ b2,
                                             float* __restrict__ out) {
    __shared__ float w2s[4096];
    int tid = threadIdx.x;
    for (int i = tid; i < 4096; i += 256) w2s[i] = w2[i];
    __syncthreads();

    int pix = blockIdx.x * 64 + (tid & 63);
    int s = tid >> 6;  // 0..3 -> ocs [s*16, s*16+16)
    float acc[16];
#pragma unroll
    for (int j = 0; j < 16; ++j) acc[j] = b2[s * 16 + j];

    for (int ic = 0; ic < 64; ++ic) {
        float v = fmaxf(g_dyn[ic * 4096 + pix], 0.f);
#pragma unroll
        for (int j = 0; j < 16; ++j)
            acc[j] = fmaf(w2s[(s * 16 + j) * 64 + ic], v, acc[j]);
    }
#pragma unroll
    for (int j = 0; j < 16; ++j) {
        int o = s * 16 + j;
        out[o * 4096 + pix] = fmaxf(acc[j] + x[o * 4096 + pix], 0.f);
    }
}

// ---------------------------------------------------------------------------
extern "C" void kernel_launch(void* const* d_in, const int* in_sizes, int n_in,
                              void* d_out, int out_size) {
    const float* x       = (const float*)d_in[0];
    const int*   buckets = (const int*)  d_in[1];
    const float* w1      = (const float*)d_in[2];
    const float* b1      = (const float*)d_in[3];
    const float* emb     = (const float*)d_in[4];
    const float* w2      = (const float*)d_in[5];
    const float* b2      = (const float*)d_in[6];
    float* out = (float*)d_out;

    k_zero<<<(HPSZ + 255) / 256, 256>>>();
    k_gconv<<<64, 256>>>(x, w1, b1);
    k_dyn<<<216, 256>>>(buckets, emb);
    k_epi<<<64, 256>>>(x, w2, b2, out);
}

// round 5
// speedup vs baseline: 1.1662x; 1.1662x over previous
#include <cuda_runtime.h>

// ---------------------------------------------------------------------------
// EResidualBlockBucket: x -> grouped3x3+ReLU -> per-pixel bucket-indexed
// dynamic 3x3 conv (+per-pixel bias) -> ReLU -> 1x1 conv -> +x -> ReLU
//
// R4 profile: standalone k_epi (1x1 epilogue) was 31.8us of 88us with 7.8%
// issue / 12.5% occ (64 CTAs, latency-bound). This round fuses the epilogue
// into k_dyn: per 32-pixel chunk, the CTA already holds all 64 dyn channels
// across its 8 warps -> stage to smem, one barrier, 1x1 conv + residual +
// ReLU in-register, store final output directly. k_epi and g_dyn deleted.
// ---------------------------------------------------------------------------

#define HPW 66                 // padded image width/height
#define HPSZ (64 * HPW * HPW)  // h_pad elements: [y][x][ic], ic fastest

__device__ __align__(16) float g_hpad[HPSZ];     // padded h, pixel-major

// ---------------- K0: zero padded h buffer ---------------------------------
__global__ void k_zero(void) {
    int i = blockIdx.x * blockDim.x + threadIdx.x;
    if (i < HPSZ) g_hpad[i] = 0.0f;
}

// ---------------- K1: grouped 3x3 conv + bias + ReLU -> g_hpad -------------
// grid: 64 blocks = 4 groups x 16 tiles (16x16 px). 256 threads.
__global__ void __launch_bounds__(256) k_gconv(const float* __restrict__ x,
                                               const float* __restrict__ w1,
                                               const float* __restrict__ b1) {
    __shared__ float xs[16][18][18];   // input tile + halo, one group (16 ic)
    __shared__ float ws[16][144];      // weights for 16 oc of this group
    __shared__ float bs[16];

    int bx = blockIdx.x;
    int g = bx >> 4;                   // group 0..3
    int tile = bx & 15;
    int y0 = (tile >> 2) * 16, x0 = (tile & 3) * 16;
    int tid = threadIdx.x;

    for (int i = tid; i < 16 * 18 * 18; i += 256) {
        int ic = i / 324;
        int rem = i - ic * 324;
        int r = rem / 18, c = rem - r * 18;
        int yy = y0 - 1 + r, xx = x0 - 1 + c;
        float v = 0.f;
        if (yy >= 0 && yy < 64 && xx >= 0 && xx < 64)
            v = x[(g * 16 + ic) * 4096 + yy * 64 + xx];
        xs[ic][r][c] = v;
    }
    for (int i = tid; i < 16 * 144; i += 256) {
        int oc = i / 144;
        ws[oc][i - oc * 144] = w1[(g * 16 + oc) * 144 + (i - oc * 144)];
    }
    if (tid < 16) bs[tid] = b1[g * 16 + tid];
    __syncthreads();

    int r = tid >> 4, c = tid & 15;
    float acc[16];
#pragma unroll
    for (int j = 0; j < 16; ++j) acc[j] = bs[j];

    for (int ic = 0; ic < 16; ++ic) {
        float p[9];
#pragma unroll
        for (int dy = 0; dy < 3; ++dy)
#pragma unroll
            for (int dx = 0; dx < 3; ++dx)
                p[dy * 3 + dx] = xs[ic][r + dy][c + dx];
#pragma unroll
        for (int j = 0; j < 16; ++j) {
#pragma unroll
            for (int k = 0; k < 9; ++k)
                acc[j] = fmaf(ws[j][ic * 9 + k], p[k], acc[j]);
        }
    }
    // write pixel-major padded layout: h_pad[((y+1)*66 + (x+1))*64 + oc]
    float* dst = g_hpad + (((y0 + r + 1) * HPW) + (x0 + c + 1)) * 64 + g * 16;
#pragma unroll
    for (int j = 0; j < 16; ++j) dst[j] = fmaxf(acc[j], 0.f);
}

// ---------------- K2: bucket-grouped dynamic conv + fused epilogue ---------
// grid: 216 blocks (one per type), 256 threads (8 warps, each warp -> 8 ocs,
// lanes -> pixels of this type, processed in chunks of 32).
__global__ void __launch_bounds__(256) k_dyn(const int* __restrict__ buckets,
                                             const float* __restrict__ emb,
                                             const float* __restrict__ x,
                                             const float* __restrict__ w2,
                                             const float* __restrict__ b2,
                                             float* __restrict__ out) {
    // Shared arrays used with float4 (LDS.128/STS.128) MUST be 16B aligned.
    __shared__ __align__(16) float ws[64 * 72];  // weights: [oc][c_local]
    __shared__ __align__(16) float ps[72 * 33];  // patches: [c_local][pixel]
    __shared__ unsigned short plist[4096];
    __shared__ int s_count;
    // ds (dyn output tile, 64x33 = 8448 floats) overlays ps (9504 floats):
    // ps is dead after the final ic-chunk compute; barriers separate uses.
    float* ds = ps;

    int t = blockIdx.x;
    int tid = threadIdx.x;
    if (tid == 0) s_count = 0;
    __syncthreads();
    for (int i = tid; i < 4096; i += 256) {
        if (buckets[i] == t) {
            int p = atomicAdd(&s_count, 1);
            plist[p] = (unsigned short)i;
        }
    }
    __syncthreads();
    int n = s_count;
    if (n == 0) return;

    int lane = tid & 31;
    int oc_base = (tid >> 5) * 8;
    const float* W = emb + (size_t)t * 36928;

    for (int chunk = 0; chunk < n; chunk += 32) {
        int pi = chunk + lane;
        int mypix = plist[pi < n ? pi : n - 1];

        float acc[8];
#pragma unroll
        for (int j = 0; j < 8; ++j)
            acc[j] = __ldg(W + (oc_base + j) * 577 + 576);  // per-pixel bias

        for (int icc8 = 0; icc8 < 8; ++icc8) {
            int icc = icc8 * 8;  // ic chunk [icc, icc+8)

            // ---- stage patches: 32 px x 9 positions x 8 ic = 576 float4s
            for (int t2 = tid; t2 < 576; t2 += 256) {
                int q = t2 & 1;
                int r = t2 >> 1;          // 0..287
                int slot = r / 9;
                int pos = r - slot * 9;   // dy*3+dx
                int pj = chunk + slot;
                int pix = plist[pj < n ? pj : n - 1];
                int y = pix >> 6, xx = pix & 63;
                int dy = pos / 3, dx = pos - dy * 3;
                const float4 v = *(const float4*)(g_hpad +
                    (((y + dy) * HPW) + (xx + dx)) * 64 + icc + q * 4);
                int base_ic = q * 4;
                ps[((base_ic + 0) * 9 + pos) * 33 + slot] = v.x;
                ps[((base_ic + 1) * 9 + pos) * 33 + slot] = v.y;
                ps[((base_ic + 2) * 9 + pos) * 33 + slot] = v.z;
                ps[((base_ic + 3) * 9 + pos) * 33 + slot] = v.w;
            }
            // ---- stage weights: 64 oc x 72 c
            {
                const float* Wc = W + icc * 9;
                for (int i2 = tid; i2 < 4608; i2 += 256) {
                    int oc = i2 / 72;
                    int cl = i2 - oc * 72;
                    ws[i2] = __ldg(Wc + oc * 577 + cl);
                }
            }
            __syncthreads();

            // ---- compute: 72 c x 8 oc per warp, weights via LDS.128
            const float* psl = ps + lane;
#pragma unroll 3
            for (int c4 = 0; c4 < 72; c4 += 4) {
                float pv0 = psl[(c4 + 0) * 33];
                float pv1 = psl[(c4 + 1) * 33];
                float pv2 = psl[(c4 + 2) * 33];
                float pv3 = psl[(c4 + 3) * 33];
#pragma unroll
                for (int j = 0; j < 8; ++j) {
                    float4 w = *(const float4*)&ws[(oc_base + j) * 72 + c4];
                    acc[j] = fmaf(w.x, pv0, acc[j]);
                    acc[j] = fmaf(w.y, pv1, acc[j]);
                    acc[j] = fmaf(w.z, pv2, acc[j]);
                    acc[j] = fmaf(w.w, pv3, acc[j]);
                }
            }
            __syncthreads();   // also protects ps before ds overlay / restage
        }

        // ---- fused epilogue: ReLU -> 1x1 conv (w2) + b2 -> +x -> ReLU
        // stage post-ReLU dyn tile: ds[oc][slot], pitch 33 (conflict-free)
#pragma unroll
        for (int j = 0; j < 8; ++j)
            ds[(oc_base + j) * 33 + lane] = fmaxf(acc[j], 0.f);
        __syncthreads();

        float eacc[8];
#pragma unroll
        for (int j = 0; j < 8; ++j) eacc[j] = __ldg(b2 + oc_base + j);

#pragma unroll
        for (int blk = 0; blk < 4; ++blk) {      // 16 ic at a time
            float pv[16];
#pragma unroll
            for (int q = 0; q < 16; ++q)
                pv[q] = ds[(blk * 16 + q) * 33 + lane];
#pragma unroll
            for (int j = 0; j < 8; ++j) {
                const float4* wr = (const float4*)(w2 +
                    (oc_base + j) * 64 + blk * 16);  // uniform, L1-resident
#pragma unroll
                for (int q4 = 0; q4 < 4; ++q4) {
                    float4 w = __ldg(wr + q4);
                    eacc[j] = fmaf(w.x, pv[q4 * 4 + 0], eacc[j]);
                    eacc[j] = fmaf(w.y, pv[q4 * 4 + 1], eacc[j]);
                    eacc[j] = fmaf(w.z, pv[q4 * 4 + 2], eacc[j]);
                    eacc[j] = fmaf(w.w, pv[q4 * 4 + 3], eacc[j]);
                }
            }
        }

        if (pi < n) {
#pragma unroll
            for (int j = 0; j < 8; ++j) {
                int o = oc_base + j;
                out[o * 4096 + mypix] =
                    fmaxf(eacc[j] + __ldg(x + o * 4096 + mypix), 0.f);
            }
        }
        __syncthreads();   // ds (== ps) must drain before next chunk restages
    }
}

// ---------------------------------------------------------------------------
extern "C" void kernel_launch(void* const* d_in, const int* in_sizes, int n_in,
                              void* d_out, int out_size) {
    const float* x       = (const float*)d_in[0];
    const int*   buckets = (const int*)  d_in[1];
    const float* w1      = (const float*)d_in[2];
    const float* b1      = (const float*)d_in[3];
    const float* emb     = (const float*)d_in[4];
    const float* w2      = (const float*)d_in[5];
    const float* b2      = (const float*)d_in[6];
    float* out = (float*)d_out;

    k_zero<<<(HPSZ + 255) / 256, 256>>>();
    k_gconv<<<64, 256>>>(x, w1, b1);
    k_dyn<<<216, 256>>>(buckets, emb, x, w2, b2, out);
}